// round 12
// baseline (speedup 1.0000x reference)
#include <cuda_runtime.h>

#define WIDTH  1024
#define HEIGHT 1024
#define RPB    16         // rows per strip (must divide HEIGHT)

// One partial per image-strip. 32*1024/16 = 2048 for the nominal shape.
__device__ float g_partials[65536];

struct RowData {
    float4 v;      // 4 target values at columns c..c+3
    float  hl, hr; // column halo (c-1 clamped, c+4 clamped)
};

__device__ __forceinline__ RowData load_row(const float* __restrict__ r,
                                            int c, int cl, int cr)
{
    RowData d;
    d.v  = *reinterpret_cast<const float4*>(r + c);
    d.hl = r[cl];
    d.hr = r[cr];
    return d;
}

// PERSISTENT grid-stride version of the R11 body: a fixed grid of blocks
// loops over strips, eliminating wave quantization (2048 strips / ~888
// concurrent blocks = 2.31 ragged waves otherwise). Per-strip work and the
// strip->partial mapping are unchanged -> bit-identical result.
// Binary-mask morphology: boundary <=> clamped 3x3 window sum in (0,9).
// BCE with t in {0,1}: bce = -log(t ? p : 1-p)  -> one __logf per pixel.
__global__ void __launch_bounds__(256)
loss_kernel(const float* __restrict__ pred, const float* __restrict__ tgt,
            int n_strips)
{
    const int c  = threadIdx.x << 2;
    const int cl = (c == 0) ? 0 : c - 1;
    const int cr = (c + 4 >= WIDTH) ? (WIDTH - 1) : (c + 4);

    for (int strip = blockIdx.x; strip < n_strips; strip += gridDim.x) {
        const int row0 = strip * RPB;
        const int y0   = row0 & (HEIGHT - 1);   // strip never crosses images

        const float* tbase = tgt  + (size_t)row0 * WIDTH;
        const float* pbase = pred + (size_t)row0 * WIDTH;

        RowData a_prev = load_row((y0 == 0) ? tbase : tbase - WIDTH, c, cl, cr);
        RowData a_cur  = load_row(tbase, c, cl, cr);

        float acc = 0.0f;   // accumulates +w*log(arg); negated at the end

        #pragma unroll
        for (int i = 0; i < RPB; i++) {
            const int y = y0 + i;
            const float* trow_next = (y == HEIGHT - 1)
                                         ? tbase + (size_t)i * WIDTH
                                         : tbase + (size_t)(i + 1) * WIDTH;
            const RowData a_next = load_row(trow_next, c, cl, cr);
            const float4  p = *reinterpret_cast<const float4*>(
                                  pbase + (size_t)i * WIDTH + c);

            const float v0 = a_prev.v.x + a_cur.v.x + a_next.v.x;
            const float v1 = a_prev.v.y + a_cur.v.y + a_next.v.y;
            const float v2 = a_prev.v.z + a_cur.v.z + a_next.v.z;
            const float v3 = a_prev.v.w + a_cur.v.w + a_next.v.w;
            const float vl = a_prev.hl  + a_cur.hl  + a_next.hl;
            const float vr = a_prev.hr  + a_cur.hr  + a_next.hr;

            const float s0 = vl + v0 + v1;
            const float s1 = v0 + v1 + v2;
            const float s2 = v1 + v2 + v3;
            const float s3 = v2 + v3 + vr;

#define PIX(S, T, P)                                                      \
            do {                                                          \
                const float arg = ((T) > 0.5f) ? (P) : (1.0f - (P));      \
                const float w   = ((S) > 0.5f && (S) < 8.5f) ? 3.0f : 1.0f; \
                acc = fmaf(w, __logf(arg), acc);                          \
            } while (0)

            PIX(s0, a_cur.v.x, p.x);
            PIX(s1, a_cur.v.y, p.y);
            PIX(s2, a_cur.v.z, p.z);
            PIX(s3, a_cur.v.w, p.w);
#undef PIX

            a_prev = a_cur;
            a_cur  = a_next;
        }

        // Block reduction: warp shuffle, then 8 warp leaders through smem.
        #pragma unroll
        for (int o = 16; o > 0; o >>= 1)
            acc += __shfl_xor_sync(0xffffffffu, acc, o);

        __shared__ float sacc[8];
        const int wid  = threadIdx.x >> 5;
        const int lane = threadIdx.x & 31;
        if (lane == 0) sacc[wid] = acc;
        __syncthreads();
        if (threadIdx.x == 0) {
            float s = 0.0f;
            #pragma unroll
            for (int i = 0; i < 8; i++) s += sacc[i];
            g_partials[strip] = -s;
        }
        __syncthreads();   // protect sacc before next loop iteration
    }
}

// Deterministic finalize with PROGRAMMATIC DEPENDENT LAUNCH: scheduled while
// loss_kernel still streams; blocks in cudaGridDependencySynchronize() until
// loss_kernel completes (all g_partials writes visible), then ~1us of work.
__global__ void __launch_bounds__(256)
finalize_kernel(float* __restrict__ out, int n_part, double inv_n)
{
    cudaGridDependencySynchronize();

    const int n4 = n_part >> 2;   // n_part divisible by 4
    double s0 = 0.0, s1 = 0.0;
    for (int i = threadIdx.x; i < n4; i += 256) {
        const float4 v = reinterpret_cast<const float4*>(g_partials)[i];
        s0 += (double)v.x + (double)v.y;
        s1 += (double)v.z + (double)v.w;
    }
    double s = s0 + s1;

    #pragma unroll
    for (int o = 16; o > 0; o >>= 1)
        s += __shfl_xor_sync(0xffffffffu, s, o);

    __shared__ double sd[8];
    const int wid  = threadIdx.x >> 5;
    const int lane = threadIdx.x & 31;
    if (lane == 0) sd[wid] = s;
    __syncthreads();
    if (threadIdx.x == 0) {
        double t = 0.0;
        #pragma unroll
        for (int i = 0; i < 8; i++) t += sd[i];
        out[0] = (float)(t * inv_n);
    }
}

extern "C" void kernel_launch(void* const* d_in, const int* in_sizes, int n_in,
                              void* d_out, int out_size)
{
    const float* pred = (const float*)d_in[0];
    const float* tgt  = (const float*)d_in[1];
    const int n      = in_sizes[0];        // B*1*H*W
    const int rows   = n / WIDTH;          // B*H
    const int strips = rows / RPB;

    // Persistent grid: 148 SMs x 6 blocks/SM (regs=40 -> 6 resident).
    int grid = 148 * 6;
    if (grid > strips) grid = strips;

    loss_kernel<<<grid, 256>>>(pred, tgt, strips);

    // Finalize with programmatic stream serialization (PDL).
    cudaLaunchConfig_t cfg = {};
    cfg.gridDim  = dim3(1, 1, 1);
    cfg.blockDim = dim3(256, 1, 1);
    cfg.dynamicSmemBytes = 0;
    cfg.stream = 0;
    cudaLaunchAttribute attrs[1];
    attrs[0].id = cudaLaunchAttributeProgrammaticStreamSerialization;
    attrs[0].val.programmaticStreamSerializationAllowed = 1;
    cfg.attrs    = attrs;
    cfg.numAttrs = 1;

    float*  out   = (float*)d_out;
    double  inv_n = 1.0 / (double)n;
    cudaLaunchKernelEx(&cfg, finalize_kernel, out, strips, inv_n);
}

// round 13
// speedup vs baseline: 1.0169x; 1.0169x over previous
#include <cuda_runtime.h>

#define WIDTH  1024
#define HEIGHT 1024
#define RPB    16         // rows per block-strip (must divide HEIGHT)

// One partial per block-strip. 32*1024/16 = 2048 for the nominal shape.
__device__ float g_partials[65536];

struct RowData {
    float4 v;      // 4 target values at columns c..c+3
    float  hl, hr; // column halo (c-1 clamped, c+4 clamped)
};

__device__ __forceinline__ RowData load_row(const float* __restrict__ r,
                                            int c, int cl, int cr)
{
    RowData d;
    d.v  = *reinterpret_cast<const float4*>(r + c);
    d.hl = r[cl];
    d.hr = r[cr];
    return d;
}

// R11 body (best: 51.1us) + __launch_bounds__(256,7): nudge ptxas to 36 regs
// so 7 blocks/SM fit (occ 71% -> ~82%), increasing outstanding loads.
// (R4's hard 32-reg cap regressed; 36 is the gentler point on that curve.)
// Binary-mask morphology: boundary <=> clamped 3x3 window sum in (0,9).
// BCE with t in {0,1}: bce = -log(t ? p : 1-p)  -> one __logf per pixel.
__global__ void __launch_bounds__(256, 7)
loss_kernel(const float* __restrict__ pred, const float* __restrict__ tgt)
{
    const int strip = blockIdx.x;
    const int row0  = strip * RPB;
    const int y0    = row0 & (HEIGHT - 1);   // strip never crosses images

    const int c  = threadIdx.x << 2;
    const int cl = (c == 0) ? 0 : c - 1;
    const int cr = (c + 4 >= WIDTH) ? (WIDTH - 1) : (c + 4);

    const float* tbase = tgt  + (size_t)row0 * WIDTH;
    const float* pbase = pred + (size_t)row0 * WIDTH;

    RowData a_prev = load_row((y0 == 0) ? tbase : tbase - WIDTH, c, cl, cr);
    RowData a_cur  = load_row(tbase, c, cl, cr);

    float acc = 0.0f;    // accumulates +w*log(arg); negated at the end

    #pragma unroll
    for (int i = 0; i < RPB; i++) {
        const int y = y0 + i;
        const float* trow_next = (y == HEIGHT - 1) ? tbase + (size_t)i * WIDTH
                                                   : tbase + (size_t)(i + 1) * WIDTH;
        const RowData a_next = load_row(trow_next, c, cl, cr);
        const float4  p = *reinterpret_cast<const float4*>(
                              pbase + (size_t)i * WIDTH + c);

        const float v0 = a_prev.v.x + a_cur.v.x + a_next.v.x;
        const float v1 = a_prev.v.y + a_cur.v.y + a_next.v.y;
        const float v2 = a_prev.v.z + a_cur.v.z + a_next.v.z;
        const float v3 = a_prev.v.w + a_cur.v.w + a_next.v.w;
        const float vl = a_prev.hl  + a_cur.hl  + a_next.hl;
        const float vr = a_prev.hr  + a_cur.hr  + a_next.hr;

        const float s0 = vl + v0 + v1;
        const float s1 = v0 + v1 + v2;
        const float s2 = v1 + v2 + v3;
        const float s3 = v2 + v3 + vr;

#define PIX(S, T, P)                                                      \
        do {                                                              \
            const float arg = ((T) > 0.5f) ? (P) : (1.0f - (P));          \
            const float w   = ((S) > 0.5f && (S) < 8.5f) ? 3.0f : 1.0f;   \
            acc = fmaf(w, __logf(arg), acc);                              \
        } while (0)

        PIX(s0, a_cur.v.x, p.x);
        PIX(s1, a_cur.v.y, p.y);
        PIX(s2, a_cur.v.z, p.z);
        PIX(s3, a_cur.v.w, p.w);
#undef PIX

        a_prev = a_cur;
        a_cur  = a_next;
    }

    // Block reduction: warp shuffle, then 8 warp leaders through smem.
    #pragma unroll
    for (int o = 16; o > 0; o >>= 1)
        acc += __shfl_xor_sync(0xffffffffu, acc, o);

    __shared__ float sacc[8];
    const int wid  = threadIdx.x >> 5;
    const int lane = threadIdx.x & 31;
    if (lane == 0) sacc[wid] = acc;
    __syncthreads();
    if (threadIdx.x == 0) {
        float s = 0.0f;
        #pragma unroll
        for (int i = 0; i < 8; i++) s += sacc[i];
        g_partials[strip] = -s;
    }
}

// Deterministic finalize with PROGRAMMATIC DEPENDENT LAUNCH: scheduled while
// loss_kernel still streams; blocks in cudaGridDependencySynchronize() until
// loss_kernel completes (all g_partials writes visible), then ~1us of work.
__global__ void __launch_bounds__(256)
finalize_kernel(float* __restrict__ out, int n_part, double inv_n)
{
    cudaGridDependencySynchronize();

    const int n4 = n_part >> 2;   // n_part divisible by 4
    double s0 = 0.0, s1 = 0.0;
    for (int i = threadIdx.x; i < n4; i += 256) {
        const float4 v = reinterpret_cast<const float4*>(g_partials)[i];
        s0 += (double)v.x + (double)v.y;
        s1 += (double)v.z + (double)v.w;
    }
    double s = s0 + s1;

    #pragma unroll
    for (int o = 16; o > 0; o >>= 1)
        s += __shfl_xor_sync(0xffffffffu, s, o);

    __shared__ double sd[8];
    const int wid  = threadIdx.x >> 5;
    const int lane = threadIdx.x & 31;
    if (lane == 0) sd[wid] = s;
    __syncthreads();
    if (threadIdx.x == 0) {
        double t = 0.0;
        #pragma unroll
        for (int i = 0; i < 8; i++) t += sd[i];
        out[0] = (float)(t * inv_n);
    }
}

extern "C" void kernel_launch(void* const* d_in, const int* in_sizes, int n_in,
                              void* d_out, int out_size)
{
    const float* pred = (const float*)d_in[0];
    const float* tgt  = (const float*)d_in[1];
    const int n      = in_sizes[0];        // B*1*H*W
    const int rows   = n / WIDTH;          // B*H
    const int strips = rows / RPB;

    loss_kernel<<<strips, 256>>>(pred, tgt);

    // Finalize with programmatic stream serialization (PDL).
    cudaLaunchConfig_t cfg = {};
    cfg.gridDim  = dim3(1, 1, 1);
    cfg.blockDim = dim3(256, 1, 1);
    cfg.dynamicSmemBytes = 0;
    cfg.stream = 0;
    cudaLaunchAttribute attrs[1];
    attrs[0].id = cudaLaunchAttributeProgrammaticStreamSerialization;
    attrs[0].val.programmaticStreamSerializationAllowed = 1;
    cfg.attrs    = attrs;
    cfg.numAttrs = 1;

    float*  out   = (float*)d_out;
    double  inv_n = 1.0 / (double)n;
    cudaLaunchKernelEx(&cfg, finalize_kernel, out, strips, inv_n);
}

// round 14
// speedup vs baseline: 1.1237x; 1.1050x over previous
#include <cuda_runtime.h>

#define WIDTH  1024
#define HEIGHT 1024
#define RPB    16         // rows per block-strip (must divide HEIGHT)

// One partial per block-strip. 32*1024/16 = 2048 for the nominal shape.
__device__ float g_partials[65536];

struct RowData {
    float4 v;      // 4 target values at columns c..c+3
    float  hl, hr; // column halo (c-1 clamped, c+4 clamped)
};

__device__ __forceinline__ RowData load_row(const float* __restrict__ r,
                                            int c, int cl, int cr)
{
    RowData d;
    d.v  = *reinterpret_cast<const float4*>(r + c);
    d.hl = r[cl];
    d.hr = r[cr];
    return d;
}

// R11 body (best: 51.1us) with LOG BATCHING: instead of 4 __logf per 4-pixel
// group, accumulate two products (weight-1 args and weight-3 args; pixels of
// the other class contribute exactly 1.0) and take 2 logs:
//   sum w_i*log(arg_i) = log(prod arg_i | w=1) + 3*log(prod arg_i | w=3)
// MUFU traffic halves; extra FMULs ride the underloaded fma pipe (19%).
// Underflow-safe: arg >= 1e-6 -> 4-term product >= 1e-24 >> FLT_MIN.
// Binary-mask morphology: boundary <=> clamped 3x3 window sum in (0,9).
__global__ void __launch_bounds__(256)
loss_kernel(const float* __restrict__ pred, const float* __restrict__ tgt)
{
    const int strip = blockIdx.x;
    const int row0  = strip * RPB;
    const int y0    = row0 & (HEIGHT - 1);   // strip never crosses images

    const int c  = threadIdx.x << 2;
    const int cl = (c == 0) ? 0 : c - 1;
    const int cr = (c + 4 >= WIDTH) ? (WIDTH - 1) : (c + 4);

    const float* tbase = tgt  + (size_t)row0 * WIDTH;
    const float* pbase = pred + (size_t)row0 * WIDTH;

    RowData a_prev = load_row((y0 == 0) ? tbase : tbase - WIDTH, c, cl, cr);
    RowData a_cur  = load_row(tbase, c, cl, cr);

    float acc = 0.0f;    // accumulates +w*log(arg); negated at the end

    #pragma unroll
    for (int i = 0; i < RPB; i++) {
        const int y = y0 + i;
        const float* trow_next = (y == HEIGHT - 1) ? tbase + (size_t)i * WIDTH
                                                   : tbase + (size_t)(i + 1) * WIDTH;
        const RowData a_next = load_row(trow_next, c, cl, cr);
        const float4  p = *reinterpret_cast<const float4*>(
                              pbase + (size_t)i * WIDTH + c);

        const float v0 = a_prev.v.x + a_cur.v.x + a_next.v.x;
        const float v1 = a_prev.v.y + a_cur.v.y + a_next.v.y;
        const float v2 = a_prev.v.z + a_cur.v.z + a_next.v.z;
        const float v3 = a_prev.v.w + a_cur.v.w + a_next.v.w;
        const float vl = a_prev.hl  + a_cur.hl  + a_next.hl;
        const float vr = a_prev.hr  + a_cur.hr  + a_next.hr;

        const float s0 = vl + v0 + v1;
        const float s1 = v0 + v1 + v2;
        const float s2 = v1 + v2 + v3;
        const float s3 = v2 + v3 + vr;

        // Per-pixel BCE argument (t in {0,1}): arg = t ? p : 1-p.
        const float arg0 = (a_cur.v.x > 0.5f) ? p.x : 1.0f - p.x;
        const float arg1 = (a_cur.v.y > 0.5f) ? p.y : 1.0f - p.y;
        const float arg2 = (a_cur.v.z > 0.5f) ? p.z : 1.0f - p.z;
        const float arg3 = (a_cur.v.w > 0.5f) ? p.w : 1.0f - p.w;

        // Boundary predicate per pixel.
        const bool b0 = (s0 > 0.5f) && (s0 < 8.5f);
        const bool b1 = (s1 > 0.5f) && (s1 < 8.5f);
        const bool b2 = (s2 > 0.5f) && (s2 < 8.5f);
        const bool b3 = (s3 > 0.5f) && (s3 < 8.5f);

        // Batch: weight-1 pixels into P1, weight-3 pixels into P3.
        const float P1 = (b0 ? 1.0f : arg0) * (b1 ? 1.0f : arg1)
                       * (b2 ? 1.0f : arg2) * (b3 ? 1.0f : arg3);
        const float P3 = (b0 ? arg0 : 1.0f) * (b1 ? arg1 : 1.0f)
                       * (b2 ? arg2 : 1.0f) * (b3 ? arg3 : 1.0f);

        acc += __logf(P1);
        acc  = fmaf(3.0f, __logf(P3), acc);

        a_prev = a_cur;
        a_cur  = a_next;
    }

    // Block reduction: warp shuffle, then 8 warp leaders through smem.
    #pragma unroll
    for (int o = 16; o > 0; o >>= 1)
        acc += __shfl_xor_sync(0xffffffffu, acc, o);

    __shared__ float sacc[8];
    const int wid  = threadIdx.x >> 5;
    const int lane = threadIdx.x & 31;
    if (lane == 0) sacc[wid] = acc;
    __syncthreads();
    if (threadIdx.x == 0) {
        float s = 0.0f;
        #pragma unroll
        for (int i = 0; i < 8; i++) s += sacc[i];
        g_partials[strip] = -s;
    }
}

// Deterministic finalize with PROGRAMMATIC DEPENDENT LAUNCH: scheduled while
// loss_kernel still streams; blocks in cudaGridDependencySynchronize() until
// loss_kernel completes (all g_partials writes visible), then ~1us of work.
__global__ void __launch_bounds__(256)
finalize_kernel(float* __restrict__ out, int n_part, double inv_n)
{
    cudaGridDependencySynchronize();

    const int n4 = n_part >> 2;   // n_part divisible by 4
    double s0 = 0.0, s1 = 0.0;
    for (int i = threadIdx.x; i < n4; i += 256) {
        const float4 v = reinterpret_cast<const float4*>(g_partials)[i];
        s0 += (double)v.x + (double)v.y;
        s1 += (double)v.z + (double)v.w;
    }
    double s = s0 + s1;

    #pragma unroll
    for (int o = 16; o > 0; o >>= 1)
        s += __shfl_xor_sync(0xffffffffu, s, o);

    __shared__ double sd[8];
    const int wid  = threadIdx.x >> 5;
    const int lane = threadIdx.x & 31;
    if (lane == 0) sd[wid] = s;
    __syncthreads();
    if (threadIdx.x == 0) {
        double t = 0.0;
        #pragma unroll
        for (int i = 0; i < 8; i++) t += sd[i];
        out[0] = (float)(t * inv_n);
    }
}

extern "C" void kernel_launch(void* const* d_in, const int* in_sizes, int n_in,
                              void* d_out, int out_size)
{
    const float* pred = (const float*)d_in[0];
    const float* tgt  = (const float*)d_in[1];
    const int n      = in_sizes[0];        // B*1*H*W
    const int rows   = n / WIDTH;          // B*H
    const int strips = rows / RPB;

    loss_kernel<<<strips, 256>>>(pred, tgt);

    // Finalize with programmatic stream serialization (PDL).
    cudaLaunchConfig_t cfg = {};
    cfg.gridDim  = dim3(1, 1, 1);
    cfg.blockDim = dim3(256, 1, 1);
    cfg.dynamicSmemBytes = 0;
    cfg.stream = 0;
    cudaLaunchAttribute attrs[1];
    attrs[0].id = cudaLaunchAttributeProgrammaticStreamSerialization;
    attrs[0].val.programmaticStreamSerializationAllowed = 1;
    cfg.attrs    = attrs;
    cfg.numAttrs = 1;

    float*  out   = (float*)d_out;
    double  inv_n = 1.0 / (double)n;
    cudaLaunchKernelEx(&cfg, finalize_kernel, out, strips, inv_n);
}